// round 4
// baseline (speedup 1.0000x reference)
#include <cuda_runtime.h>

#define SS 512
#define EE 128
#define NWARP 16
#define THREADS 512
#define VOCAB 100000

// ---------------- K1: per-vocab scalar  lp[v] = (emb[v].Wq + bq) * sum(emb[v]) ----
// 256 threads = 8 warps, each warp handles 4 rows (unrolled -> 4 independent
// load+shuffle chains for ILP). grid = 100000 / 32 = 3125 blocks.
__global__ __launch_bounds__(256)
void vocab_lp_kernel(const float* __restrict__ emb,
                     const float* __restrict__ Wq,
                     const float* __restrict__ bq,
                     float* __restrict__ lp)
{
    const int w = threadIdx.x >> 5;
    const int l = threadIdx.x & 31;
    const float4 wq4 = reinterpret_cast<const float4*>(Wq)[l];
    const float bq0 = bq[0];

    const int base = blockIdx.x * 32 + w * 4;
    #pragma unroll
    for (int i = 0; i < 4; i++) {
        const int v = base + i;                     // grid sized exactly: always < VOCAB
        const float4 r = reinterpret_cast<const float4*>(emb + (size_t)v * EE)[l];
        float dot = r.x * wq4.x + r.y * wq4.y + r.z * wq4.z + r.w * wq4.w;
        float sm  = (r.x + r.y) + (r.z + r.w);
        #pragma unroll
        for (int o = 16; o; o >>= 1) {
            dot += __shfl_xor_sync(0xffffffffu, dot, o);
            sm  += __shfl_xor_sync(0xffffffffu, sm,  o);
        }
        if (l == 0) lp[v] = (dot + bq0) * sm;
    }
}

// ---------------- K2: softmax over lp-gather + weighted pool + head -----------
__global__ __launch_bounds__(THREADS, 2)
void pool_kernel(const int* __restrict__ x,
                 const float* __restrict__ emb,
                 const float* __restrict__ lp,
                 const float* __restrict__ Wm,
                 const float* __restrict__ bm,
                 float* __restrict__ out)
{
    __shared__ float s_p[SS];
    __shared__ int   s_idx[SS];
    __shared__ float s_th[NWARP][EE];
    __shared__ float s_red[32];

    const int b   = blockIdx.x;
    const int tid = threadIdx.x;
    const int w   = tid >> 5;
    const int l   = tid & 31;

    // one thread per token: gather id + scalar logit (4B each) -- no reductions
    const int idx = x[b * SS + tid];
    s_idx[tid] = idx;
    const float v = lp[idx];

    // ---------------- block softmax over S ----------------
    float m = v;
    #pragma unroll
    for (int o = 16; o; o >>= 1) m = fmaxf(m, __shfl_xor_sync(0xffffffffu, m, o));
    if (l == 0) s_red[w] = m;
    __syncthreads();
    if (w == 0) {
        float mm = (l < NWARP) ? s_red[l] : -3.4e38f;
        #pragma unroll
        for (int o = 16; o; o >>= 1) mm = fmaxf(mm, __shfl_xor_sync(0xffffffffu, mm, o));
        if (l == 0) s_red[0] = mm;
    }
    __syncthreads();
    m = s_red[0];
    __syncthreads();                       // all readers done before s_red reuse

    const float e = expf(v - m);
    float sum = e;
    #pragma unroll
    for (int o = 16; o; o >>= 1) sum += __shfl_xor_sync(0xffffffffu, sum, o);
    if (l == 0) s_red[w] = sum;
    __syncthreads();
    if (w == 0) {
        float ss2 = (l < NWARP) ? s_red[l] : 0.f;
        #pragma unroll
        for (int o = 16; o; o >>= 1) ss2 += __shfl_xor_sync(0xffffffffu, ss2, o);
        if (l == 0) s_red[0] = ss2;
    }
    __syncthreads();
    s_p[tid] = e * (1.0f / s_red[0]);
    __syncthreads();

    // ---------------- weighted pool: t_hat = sum_s p[s] * emb[x[s]] ----------------
    float4 acc = make_float4(0.f, 0.f, 0.f, 0.f);
    #pragma unroll 4
    for (int s = w; s < SS; s += NWARP) {
        const float ps = s_p[s];
        const float4 vv = reinterpret_cast<const float4*>(emb + (size_t)s_idx[s] * EE)[l];
        acc.x = fmaf(ps, vv.x, acc.x);
        acc.y = fmaf(ps, vv.y, acc.y);
        acc.z = fmaf(ps, vv.z, acc.z);
        acc.w = fmaf(ps, vv.w, acc.w);
    }
    reinterpret_cast<float4*>(&s_th[w][4 * l])[0] = acc;
    __syncthreads();

    // ---------------- reduce partials + MLP head + relu ----------------
    if (tid < EE) {
        float t = 0.f;
        #pragma unroll
        for (int ww = 0; ww < NWARP; ww++) t += s_th[ww][tid];
        float p0 = t * Wm[tid * 2 + 0];
        float p1 = t * Wm[tid * 2 + 1];
        #pragma unroll
        for (int o = 16; o; o >>= 1) {
            p0 += __shfl_xor_sync(0xffffffffu, p0, o);
            p1 += __shfl_xor_sync(0xffffffffu, p1, o);
        }
        if (l == 0) {
            s_red[w * 2 + 0] = p0;
            s_red[w * 2 + 1] = p1;
        }
    }
    __syncthreads();
    if (tid == 0) {
        float o0 = (s_red[0] + s_red[2]) + (s_red[4] + s_red[6]) + bm[0];
        float o1 = (s_red[1] + s_red[3]) + (s_red[5] + s_red[7]) + bm[1];
        out[b * 2 + 0] = fmaxf(o0, 0.f);
        out[b * 2 + 1] = fmaxf(o1, 0.f);
    }
}

// scratch for per-vocab logits (device global: no allocation allowed)
__device__ float g_lp[VOCAB];

extern "C" void kernel_launch(void* const* d_in, const int* in_sizes, int n_in,
                              void* d_out, int out_size)
{
    const int*   x   = (const int*)  d_in[0];
    const float* emb = (const float*)d_in[1];
    const float* Wq  = (const float*)d_in[2];
    const float* bq  = (const float*)d_in[3];
    const float* Wm  = (const float*)d_in[4];
    const float* bm  = (const float*)d_in[5];
    float* out = (float*)d_out;

    float* lp;
    cudaGetSymbolAddress((void**)&lp, g_lp);

    vocab_lp_kernel<<<VOCAB / 32, 256>>>(emb, Wq, bq, lp);
    pool_kernel<<<256, THREADS>>>(x, emb, lp, Wm, bm, out);
}

// round 5
// speedup vs baseline: 1.4157x; 1.4157x over previous
#include <cuda_runtime.h>

#define SS 512
#define EE 128
#define NW 8            // warps per block
#define THREADS 256
#define GRPA 8          // prefetch depth, logit phase
#define GRPC 16         // prefetch depth, pool phase

__global__ __launch_bounds__(THREADS, 2)
void fused_kernel(const int* __restrict__ x,
                  const float* __restrict__ emb,
                  const float* __restrict__ Wq,
                  const float* __restrict__ bq,
                  const float* __restrict__ Wm,
                  const float* __restrict__ bm,
                  float* __restrict__ out)
{
    __shared__ float s_p[SS];          // log_p -> p
    __shared__ int   s_idx[SS];
    __shared__ float s_th[NW][EE];     // per-warp partial t_hat
    __shared__ float s_red[32];

    const int b   = blockIdx.x;
    const int tid = threadIdx.x;
    const int w   = tid >> 5;
    const int l   = tid & 31;

    // token ids: 2 per thread, vectorized
    reinterpret_cast<int2*>(s_idx)[tid] =
        reinterpret_cast<const int2*>(x + (size_t)b * SS)[tid];
    const float4 wq4 = reinterpret_cast<const float4*>(Wq)[l];
    const float bq0 = bq[0];
    __syncthreads();

    // ---------- Phase A: log_p[s] = (row.Wq + bq) * sum(row) ----------
    // warp w owns tokens s = w + i*NW, i in [0,64). Prefetch GRPA rows, then reduce.
    for (int g = 0; g < 64; g += GRPA) {
        float4 r[GRPA];
        #pragma unroll
        for (int i = 0; i < GRPA; i++) {
            const int s = w + (g + i) * NW;
            r[i] = reinterpret_cast<const float4*>(emb + (size_t)s_idx[s] * EE)[l];
        }
        #pragma unroll
        for (int i = 0; i < GRPA; i++) {
            float dot = r[i].x * wq4.x + r[i].y * wq4.y + r[i].z * wq4.z + r[i].w * wq4.w;
            float sm  = (r[i].x + r[i].y) + (r[i].z + r[i].w);
            #pragma unroll
            for (int o = 16; o; o >>= 1) {
                dot += __shfl_xor_sync(0xffffffffu, dot, o);
                sm  += __shfl_xor_sync(0xffffffffu, sm,  o);
            }
            if (l == 0) s_p[w + (g + i) * NW] = (dot + bq0) * sm;
        }
    }
    __syncthreads();

    // ---------- Phase B: softmax over S (2 values per thread) ----------
    const float va = s_p[tid];
    const float vb = s_p[tid + 256];
    float m = fmaxf(va, vb);
    #pragma unroll
    for (int o = 16; o; o >>= 1) m = fmaxf(m, __shfl_xor_sync(0xffffffffu, m, o));
    if (l == 0) s_red[w] = m;
    __syncthreads();
    if (w == 0) {
        float mm = (l < NW) ? s_red[l] : -3.4e38f;
        #pragma unroll
        for (int o = 16; o; o >>= 1) mm = fmaxf(mm, __shfl_xor_sync(0xffffffffu, mm, o));
        if (l == 0) s_red[0] = mm;
    }
    __syncthreads();
    m = s_red[0];
    __syncthreads();   // everyone read s_red[0] before reuse

    const float e0 = expf(va - m);
    const float e1 = expf(vb - m);
    float sum = e0 + e1;
    #pragma unroll
    for (int o = 16; o; o >>= 1) sum += __shfl_xor_sync(0xffffffffu, sum, o);
    if (l == 0) s_red[w] = sum;
    __syncthreads();
    if (w == 0) {
        float ss = (l < NW) ? s_red[l] : 0.f;
        #pragma unroll
        for (int o = 16; o; o >>= 1) ss += __shfl_xor_sync(0xffffffffu, ss, o);
        if (l == 0) s_red[0] = ss;
    }
    __syncthreads();
    const float inv = 1.0f / s_red[0];
    s_p[tid]       = e0 * inv;
    s_p[tid + 256] = e1 * inv;
    __syncthreads();

    // ---------- Phase C: t_hat = sum_s p[s] * emb[x[s]], MLP=GRPC ----------
    float4 acc = make_float4(0.f, 0.f, 0.f, 0.f);
    for (int g = 0; g < 64; g += GRPC) {
        float4 r[GRPC];
        float  p[GRPC];
        #pragma unroll
        for (int i = 0; i < GRPC; i++) {
            const int s = w + (g + i) * NW;
            p[i] = s_p[s];
            r[i] = reinterpret_cast<const float4*>(emb + (size_t)s_idx[s] * EE)[l];
        }
        #pragma unroll
        for (int i = 0; i < GRPC; i++) {
            acc.x = fmaf(p[i], r[i].x, acc.x);
            acc.y = fmaf(p[i], r[i].y, acc.y);
            acc.z = fmaf(p[i], r[i].z, acc.z);
            acc.w = fmaf(p[i], r[i].w, acc.w);
        }
    }
    reinterpret_cast<float4*>(&s_th[w][4 * l])[0] = acc;
    __syncthreads();

    // ---------- Phase D: reduce partials + MLP head + relu ----------
    if (tid < EE) {                       // warps 0..3
        float t = 0.f;
        #pragma unroll
        for (int ww = 0; ww < NW; ww++) t += s_th[ww][tid];
        float p0 = t * Wm[tid * 2 + 0];
        float p1 = t * Wm[tid * 2 + 1];
        #pragma unroll
        for (int o = 16; o; o >>= 1) {
            p0 += __shfl_xor_sync(0xffffffffu, p0, o);
            p1 += __shfl_xor_sync(0xffffffffu, p1, o);
        }
        if (l == 0) {
            s_red[w * 2 + 0] = p0;
            s_red[w * 2 + 1] = p1;
        }
    }
    __syncthreads();
    if (tid == 0) {
        float o0 = (s_red[0] + s_red[2]) + (s_red[4] + s_red[6]) + bm[0];
        float o1 = (s_red[1] + s_red[3]) + (s_red[5] + s_red[7]) + bm[1];
        out[b * 2 + 0] = fmaxf(o0, 0.f);
        out[b * 2 + 1] = fmaxf(o1, 0.f);
    }
}

extern "C" void kernel_launch(void* const* d_in, const int* in_sizes, int n_in,
                              void* d_out, int out_size)
{
    const int*   x   = (const int*)  d_in[0];
    const float* emb = (const float*)d_in[1];
    const float* Wq  = (const float*)d_in[2];
    const float* bq  = (const float*)d_in[3];
    const float* Wm  = (const float*)d_in[4];
    const float* bm  = (const float*)d_in[5];
    float* out = (float*)d_out;

    fused_kernel<<<256, THREADS>>>(x, emb, Wq, bq, Wm, bm, out);
}